// round 4
// baseline (speedup 1.0000x reference)
#include <cuda_runtime.h>
#include <cuda_bf16.h>
#include <cstdint>

// W8A16 linear via 2-level residual int8 quantization + IMMA (compute_103-safe).
// out[M,N] = (x[M,K] @ W[N,K]^T) * scales[N] + bias[N]
//   x fp32 -> per-row q1,q2 int8 (x ~= s1*q1 + s2*q2, s2 = s1/254)
//   W int8 (delivered as int32 buffer) -> int8 scratch
//   GEMM: two exact int32 IMMA accumulations, combined in fp32 epilogue.
// Tiling: CTA 128x128, BK=64, 8 warps x (32x64), cp.async double buffer.

#define GK 4096
#define GM 4096
#define GN 11008

__device__ int8_t g_q1[GM * GK];
__device__ int8_t g_q2[GM * GK];
__device__ int8_t g_w8[(size_t)GN * GK];
__device__ float2 g_rs[GM];        // {s1, s2} per activation row

// ---------------- helpers ----------------
__device__ __forceinline__ uint32_t s2u(const void* p) {
    uint32_t a;
    asm("{ .reg .u64 t; cvta.to.shared.u64 t, %1; cvt.u32.u64 %0, t; }" : "=r"(a) : "l"(p));
    return a;
}
#define CP_ASYNC16(dst, src) \
    asm volatile("cp.async.cg.shared.global [%0], [%1], 16;" :: "r"(dst), "l"(src))
#define CP_COMMIT() asm volatile("cp.async.commit_group;" ::: "memory")
#define CP_WAIT(n)  asm volatile("cp.async.wait_group %0;" :: "n"(n) : "memory")

__device__ __forceinline__ float clamp127(float v) {
    return fminf(fmaxf(v, -127.0f), 127.0f);
}

// ---------------- W prequant: int32 -> int8 ----------------
__global__ void wprequant_kernel(const int* __restrict__ w, int n4) {
    int stride = gridDim.x * blockDim.x;
    for (int i = blockIdx.x * blockDim.x + threadIdx.x; i < n4; i += stride) {
        int4 v = reinterpret_cast<const int4*>(w)[i];
        char4 c;
        c.x = (char)v.x; c.y = (char)v.y; c.z = (char)v.z; c.w = (char)v.w;
        reinterpret_cast<char4*>(g_w8)[i] = c;
    }
}

// ---------------- A quant: one row per block ----------------
__global__ __launch_bounds__(256)
void aquant_kernel(const float* __restrict__ x, int K) {
    __shared__ float red[8];
    const int row = blockIdx.x;
    const int tid = threadIdx.x;
    const float4* xr = reinterpret_cast<const float4*>(x + (size_t)row * K);

    float4 v[4];
    float m = 0.0f;
    #pragma unroll
    for (int it = 0; it < 4; ++it) {
        v[it] = xr[tid + it * 256];
        m = fmaxf(m, fmaxf(fmaxf(fabsf(v[it].x), fabsf(v[it].y)),
                           fmaxf(fabsf(v[it].z), fabsf(v[it].w))));
    }
    #pragma unroll
    for (int o = 16; o > 0; o >>= 1)
        m = fmaxf(m, __shfl_xor_sync(0xffffffffu, m, o));
    if ((tid & 31) == 0) red[tid >> 5] = m;
    __syncthreads();
    if (tid < 32) {
        float t = (tid < 8) ? red[tid] : 0.0f;
        #pragma unroll
        for (int o = 4; o > 0; o >>= 1)
            t = fmaxf(t, __shfl_xor_sync(0xffffffffu, t, o));
        if (tid == 0) red[0] = fmaxf(t, 1e-30f);
    }
    __syncthreads();
    m = red[0];

    const float s1  = m * (1.0f / 127.0f);
    const float is1 = 127.0f / m;
    const float s2  = s1 * (1.0f / 254.0f);
    const float is2 = 254.0f / s1;

    char4* q1o = reinterpret_cast<char4*>(g_q1) + (size_t)row * (K / 4);
    char4* q2o = reinterpret_cast<char4*>(g_q2) + (size_t)row * (K / 4);

    #pragma unroll
    for (int it = 0; it < 4; ++it) {
        float4 a = v[it];
        float q1x = clamp127(rintf(a.x * is1));
        float q1y = clamp127(rintf(a.y * is1));
        float q1z = clamp127(rintf(a.z * is1));
        float q1w = clamp127(rintf(a.w * is1));
        float rx = fmaf(-q1x, s1, a.x);
        float ry = fmaf(-q1y, s1, a.y);
        float rz = fmaf(-q1z, s1, a.z);
        float rw = fmaf(-q1w, s1, a.w);
        char4 c1, c2;
        c1.x = (char)(int)q1x; c1.y = (char)(int)q1y;
        c1.z = (char)(int)q1z; c1.w = (char)(int)q1w;
        c2.x = (char)(int)clamp127(rintf(rx * is2));
        c2.y = (char)(int)clamp127(rintf(ry * is2));
        c2.z = (char)(int)clamp127(rintf(rz * is2));
        c2.w = (char)(int)clamp127(rintf(rw * is2));
        q1o[tid + it * 256] = c1;
        q2o[tid + it * 256] = c2;
    }
    if (tid == 0) g_rs[row] = make_float2(s1, s2);
}

// ---------------- IMMA GEMM ----------------
#define BM 128
#define BN 128
#define BK 64
#define RSTR 80                       // smem row stride bytes (conflict-free)
#define TILEB (BM * RSTR)             // 10240
#define STAGEB (3 * TILEB)            // 30720
#define SMEMB (2 * STAGEB)            // 61440

__global__ __launch_bounds__(256, 1)
void w8a16_imma_kernel(const float* __restrict__ scales,
                       const float* __restrict__ bias,
                       float* __restrict__ out,
                       int M, int N, int K)
{
    extern __shared__ char sm[];
    const uint32_t sb = s2u(sm);
    const int tid  = threadIdx.x;
    const int lane = tid & 31;
    const int warp = tid >> 5;
    const int wm = warp >> 1;         // 0..3 -> m offset 32*wm
    const int wn = warp & 1;          // 0..1 -> n offset 64*wn

    const int mbase = blockIdx.y * BM;
    const int nbase = blockIdx.x * BN;

    const int8_t* a1g = g_q1 + (size_t)mbase * K;
    const int8_t* a2g = g_q2 + (size_t)mbase * K;
    const int8_t* bg  = g_w8 + (size_t)nbase * K;

    int acc[2][2][8][4];
    #pragma unroll
    for (int p = 0; p < 2; ++p)
        #pragma unroll
        for (int mi = 0; mi < 2; ++mi)
            #pragma unroll
            for (int ni = 0; ni < 8; ++ni)
                #pragma unroll
                for (int c = 0; c < 4; ++c)
                    acc[p][mi][ni][c] = 0;

    const int nch = K / BK;           // 64

    // issue loads for one stage: 1536 16B chunks, 6 per thread
    #define ISSUE_STAGE(st, k0) do {                                             \
        uint32_t dstb = sb + (st) * STAGEB;                                      \
        _Pragma("unroll")                                                        \
        for (int cc = 0; cc < 6; ++cc) {                                         \
            int cid  = tid + cc * 256;          /* 0..1535 */                    \
            int tile = cid >> 9;                                                 \
            int rem  = cid & 511;                                                \
            int row  = rem >> 2;                                                 \
            int cq   = rem & 3;                                                  \
            const int8_t* src =                                                  \
                (tile == 0 ? a1g : (tile == 1 ? a2g : bg))                       \
                + (size_t)row * K + (k0) + cq * 16;                              \
            CP_ASYNC16(dstb + tile * TILEB + row * RSTR + cq * 16, src);         \
        }                                                                        \
        CP_COMMIT();                                                             \
    } while (0)

    ISSUE_STAGE(0, 0);

    for (int i = 0; i < nch; ++i) {
        const int st = i & 1;
        if (i + 1 < nch) {
            ISSUE_STAGE(st ^ 1, (i + 1) * BK);
            CP_WAIT(1);
        } else {
            CP_WAIT(0);
        }
        __syncthreads();

        const uint32_t a1s = sb + st * STAGEB;
        const uint32_t a2s = a1s + TILEB;
        const uint32_t bs  = a1s + 2 * TILEB;
        const int rq = lane >> 2;            // 0..7
        const int cq = (lane & 3) << 2;      // byte col 0,4,8,12

        #pragma unroll
        for (int s = 0; s < 2; ++s) {        // k32 steps
            const int kb = s * 32 + cq;
            uint32_t bf[8][2];
            #pragma unroll
            for (int ni = 0; ni < 8; ++ni) {
                uint32_t ad = bs + (wn * 64 + ni * 8 + rq) * RSTR + kb;
                asm volatile("ld.shared.b32 %0, [%1];" : "=r"(bf[ni][0]) : "r"(ad));
                asm volatile("ld.shared.b32 %0, [%1];" : "=r"(bf[ni][1]) : "r"(ad + 16));
            }
            #pragma unroll
            for (int p = 0; p < 2; ++p) {
                const uint32_t as = p ? a2s : a1s;
                #pragma unroll
                for (int mi = 0; mi < 2; ++mi) {
                    uint32_t af[4];
                    uint32_t ad = as + (wm * 32 + mi * 16 + rq) * RSTR + kb;
                    asm volatile("ld.shared.b32 %0, [%1];" : "=r"(af[0]) : "r"(ad));
                    asm volatile("ld.shared.b32 %0, [%1];" : "=r"(af[1]) : "r"(ad + 8 * RSTR));
                    asm volatile("ld.shared.b32 %0, [%1];" : "=r"(af[2]) : "r"(ad + 16));
                    asm volatile("ld.shared.b32 %0, [%1];" : "=r"(af[3]) : "r"(ad + 8 * RSTR + 16));
                    #pragma unroll
                    for (int ni = 0; ni < 8; ++ni) {
                        asm volatile(
                            "mma.sync.aligned.m16n8k32.row.col.s32.s8.s8.s32 "
                            "{%0,%1,%2,%3}, {%4,%5,%6,%7}, {%8,%9}, {%0,%1,%2,%3};\n"
                            : "+r"(acc[p][mi][ni][0]), "+r"(acc[p][mi][ni][1]),
                              "+r"(acc[p][mi][ni][2]), "+r"(acc[p][mi][ni][3])
                            : "r"(af[0]), "r"(af[1]), "r"(af[2]), "r"(af[3]),
                              "r"(bf[ni][0]), "r"(bf[ni][1]));
                    }
                }
            }
        }
        __syncthreads();
    }

    // ---- epilogue ----
    #pragma unroll
    for (int mi = 0; mi < 2; ++mi) {
        const int r0 = mbase + wm * 32 + mi * 16 + (lane >> 2);
        const float2 rsA = g_rs[r0];
        const float2 rsB = g_rs[r0 + 8];
        float* o0 = out + (size_t)r0 * N + nbase;
        float* o1 = out + (size_t)(r0 + 8) * N + nbase;
        #pragma unroll
        for (int ni = 0; ni < 8; ++ni) {
            const int gn = wn * 64 + ni * 8 + ((lane & 3) << 1);
            const float s0 = scales[nbase + gn], s1c = scales[nbase + gn + 1];
            const float b0 = bias[nbase + gn],   b1c = bias[nbase + gn + 1];
            float2 v;
            v.x = ((float)acc[0][mi][ni][0] * rsA.x + (float)acc[1][mi][ni][0] * rsA.y) * s0 + b0;
            v.y = ((float)acc[0][mi][ni][1] * rsA.x + (float)acc[1][mi][ni][1] * rsA.y) * s1c + b1c;
            *reinterpret_cast<float2*>(o0 + gn) = v;
            v.x = ((float)acc[0][mi][ni][2] * rsB.x + (float)acc[1][mi][ni][2] * rsB.y) * s0 + b0;
            v.y = ((float)acc[0][mi][ni][3] * rsB.x + (float)acc[1][mi][ni][3] * rsB.y) * s1c + b1c;
            *reinterpret_cast<float2*>(o1 + gn) = v;
        }
    }
}

extern "C" void kernel_launch(void* const* d_in, const int* in_sizes, int n_in,
                              void* d_out, int out_size)
{
    const float* x      = (const float*) d_in[0];
    const int*   w      = (const int*)   d_in[1];   // int8 values in int32 storage
    const float* scales = (const float*) d_in[2];
    const float* bias   = (const float*) d_in[3];
    float*       out    = (float*)       d_out;

    const int N = in_sizes[2];            // 11008
    const int K = in_sizes[1] / N;        // 4096
    const int M = in_sizes[0] / K;        // 4096

    cudaFuncSetAttribute(w8a16_imma_kernel,
                         cudaFuncAttributeMaxDynamicSharedMemorySize, SMEMB);

    wprequant_kernel<<<2048, 256>>>(w, (N * K) / 4);
    aquant_kernel<<<M, 256>>>(x, K);
    dim3 grid(N / BN, M / BM);            // 86 x 32
    w8a16_imma_kernel<<<grid, 256, SMEMB>>>(scales, bias, out, M, N, K);
}

// round 6
// speedup vs baseline: 6.2013x; 6.2013x over previous
#include <cuda_runtime.h>
#include <cuda_fp16.h>
#include <cstdint>

// W8A16 linear, single-pass fp16 mma.sync (compute_103-safe).
// out[M,N] = (x[M,K] @ W[N,K]^T) * scales[N] + bias[N]
//   Prequant: W int8-in-int32 -> fp16 (exact); x fp32 -> fp16 (rel err 2^-11).
//   GEMM: CTA 128x128, BK=64, 8 warps x (32x64), cp.async 2-stage,
//   ldmatrix fragments (non-trans for BOTH A and B: k contiguous in smem),
//   mma.sync.m16n8k16.f32.f16.f16.f32.

#define GK 4096
#define GM 4096
#define GN 11008

__device__ __half g_xh[(size_t)GM * GK];
__device__ __half g_wh[(size_t)GN * GK];

// ---------------- helpers ----------------
__device__ __forceinline__ uint32_t s2u(const void* p) {
    uint32_t a;
    asm("{ .reg .u64 t; cvta.to.shared.u64 t, %1; cvt.u32.u64 %0, t; }" : "=r"(a) : "l"(p));
    return a;
}
#define CP_ASYNC16(dst, src) \
    asm volatile("cp.async.cg.shared.global [%0], [%1], 16;" :: "r"(dst), "l"(src))
#define CP_COMMIT() asm volatile("cp.async.commit_group;" ::: "memory")
#define CP_WAIT(n)  asm volatile("cp.async.wait_group %0;" :: "n"(n) : "memory")

#define LDSM_X4(r0, r1, r2, r3, a)                                              \
    asm volatile("ldmatrix.sync.aligned.m8n8.x4.shared.b16 {%0,%1,%2,%3}, [%4];" \
                 : "=r"(r0), "=r"(r1), "=r"(r2), "=r"(r3) : "r"(a))

// ---------------- prequant ----------------
__global__ void wprequant_kernel(const int* __restrict__ w, int n4) {
    int stride = gridDim.x * blockDim.x;
    for (int i = blockIdx.x * blockDim.x + threadIdx.x; i < n4; i += stride) {
        int4 v = reinterpret_cast<const int4*>(w)[i];
        __half2 p0 = __floats2half2_rn((float)v.x, (float)v.y);   // exact
        __half2 p1 = __floats2half2_rn((float)v.z, (float)v.w);
        uint2 pk;
        pk.x = *reinterpret_cast<uint32_t*>(&p0);
        pk.y = *reinterpret_cast<uint32_t*>(&p1);
        reinterpret_cast<uint2*>(g_wh)[i] = pk;
    }
}

__global__ void xprequant_kernel(const float* __restrict__ x, int n4) {
    int stride = gridDim.x * blockDim.x;
    for (int i = blockIdx.x * blockDim.x + threadIdx.x; i < n4; i += stride) {
        float4 v = reinterpret_cast<const float4*>(x)[i];
        __half2 p0 = __floats2half2_rn(v.x, v.y);
        __half2 p1 = __floats2half2_rn(v.z, v.w);
        uint2 pk;
        pk.x = *reinterpret_cast<uint32_t*>(&p0);
        pk.y = *reinterpret_cast<uint32_t*>(&p1);
        reinterpret_cast<uint2*>(g_xh)[i] = pk;
    }
}

// ---------------- GEMM ----------------
#define BM 128
#define BN 128
#define BK 64
#define ATILE 16384                 // 128 rows x 128 B
#define STAGEB 32768                // A + B
#define SMEMB  65536                // 2 stages

__global__ __launch_bounds__(256, 2)
void w8a16_hmma_kernel(const float* __restrict__ scales,
                       const float* __restrict__ bias,
                       float* __restrict__ out,
                       int M, int N, int K)
{
    extern __shared__ char sm[];
    const uint32_t sb = s2u(sm);
    const int tid  = threadIdx.x;
    const int lane = tid & 31;
    const int warp = tid >> 5;
    const int wm = warp >> 1;            // 0..3
    const int wn = warp & 1;             // 0..1

    const int mbase = blockIdx.y * BM;
    const int nbase = blockIdx.x * BN;

    const __half* ag  = g_xh + (size_t)mbase * K;
    const __half* bgp = g_wh + (size_t)nbase * K;

    float acc[2][8][4];
    #pragma unroll
    for (int mi = 0; mi < 2; ++mi)
        #pragma unroll
        for (int ni = 0; ni < 8; ++ni)
            #pragma unroll
            for (int c = 0; c < 4; ++c)
                acc[mi][ni][c] = 0.0f;

    // ldmatrix lane address components (non-trans x4 for both operands)
    // A: tile0 = rows m+0..7 / k-lo,   tile1 = rows m+8..15 / k-lo,
    //    tile2 = rows m+0..7 / k-hi,   tile3 = rows m+8..15 / k-hi
    const int a_rl = (lane & 7) + ((lane >> 3) & 1) * 8;   // row within m16
    const int a_cb = lane >> 4;                            // k8-chunk select
    // B: tile0 = rows n+0..7 / k-lo,   tile1 = rows n+0..7 / k-hi,
    //    tile2 = rows n+8..15 / k-lo,  tile3 = rows n+8..15 / k-hi
    const int b_rl = (lane & 7) + ((lane >> 4) << 3);      // row within n16
    const int b_cb = (lane >> 3) & 1;

    const int ar0 = wm * 32 + a_rl;            // mi=0 row
    const int ar1 = ar0 + 16;                  // mi=1 row
    const uint32_t arow0 = (uint32_t)ar0 * 128, am0 = (uint32_t)(ar0 & 7);
    const uint32_t arow1 = (uint32_t)ar1 * 128, am1 = (uint32_t)(ar1 & 7);

    uint32_t brow[4], bm7[4];
    #pragma unroll
    for (int nj = 0; nj < 4; ++nj) {
        int r = wn * 64 + nj * 16 + b_rl;
        brow[nj] = (uint32_t)r * 128;
        bm7[nj]  = (uint32_t)(r & 7);
    }

    const int nch = K / BK;                    // 64

    // issue one stage: 2048 x 16B chunks, 8 per thread
    #define ISSUE_STAGE(st, k0) do {                                             \
        uint32_t dstb = sb + (st) * STAGEB;                                      \
        _Pragma("unroll")                                                        \
        for (int cc = 0; cc < 8; ++cc) {                                         \
            int cid  = tid + cc * 256;          /* 0..2047 */                    \
            int tile = cid >> 10;               /* 0=A 1=B */                    \
            int rem  = cid & 1023;                                               \
            int row  = rem >> 3;                                                 \
            int c    = rem & 7;                                                  \
            const __half* src = (tile ? bgp : ag) + (size_t)row * K + (k0) + c * 8; \
            uint32_t dst = dstb + tile * ATILE + row * 128 +                     \
                           ((uint32_t)(c ^ (row & 7)) << 4);                     \
            CP_ASYNC16(dst, src);                                                \
        }                                                                        \
        CP_COMMIT();                                                             \
    } while (0)

    ISSUE_STAGE(0, 0);

    for (int i = 0; i < nch; ++i) {
        const int st = i & 1;
        if (i + 1 < nch) {
            ISSUE_STAGE(st ^ 1, (i + 1) * BK);
            CP_WAIT(1);
        } else {
            CP_WAIT(0);
        }
        __syncthreads();

        const uint32_t as = sb + st * STAGEB;
        const uint32_t bs = as + ATILE;

        #pragma unroll
        for (int ks = 0; ks < 4; ++ks) {
            const uint32_t kc2 = (uint32_t)(ks * 2);

            uint32_t bf[4][4];
            #pragma unroll
            for (int nj = 0; nj < 4; ++nj) {
                uint32_t addr = bs + brow[nj] + (((kc2 + b_cb) ^ bm7[nj]) << 4);
                LDSM_X4(bf[nj][0], bf[nj][1], bf[nj][2], bf[nj][3], addr);
            }

            uint32_t af0[4], af1[4];
            {
                uint32_t addr = as + arow0 + (((kc2 + a_cb) ^ am0) << 4);
                LDSM_X4(af0[0], af0[1], af0[2], af0[3], addr);
                addr = as + arow1 + (((kc2 + a_cb) ^ am1) << 4);
                LDSM_X4(af1[0], af1[1], af1[2], af1[3], addr);
            }

            #pragma unroll
            for (int nj = 0; nj < 4; ++nj) {
                #pragma unroll
                for (int h = 0; h < 2; ++h) {       // ni = nj*2 + h
                    const int ni = nj * 2 + h;
                    asm volatile(
                        "mma.sync.aligned.m16n8k16.row.col.f32.f16.f16.f32 "
                        "{%0,%1,%2,%3}, {%4,%5,%6,%7}, {%8,%9}, {%0,%1,%2,%3};\n"
                        : "+f"(acc[0][ni][0]), "+f"(acc[0][ni][1]),
                          "+f"(acc[0][ni][2]), "+f"(acc[0][ni][3])
                        : "r"(af0[0]), "r"(af0[1]), "r"(af0[2]), "r"(af0[3]),
                          "r"(bf[nj][h * 2]), "r"(bf[nj][h * 2 + 1]));
                    asm volatile(
                        "mma.sync.aligned.m16n8k16.row.col.f32.f16.f16.f32 "
                        "{%0,%1,%2,%3}, {%4,%5,%6,%7}, {%8,%9}, {%0,%1,%2,%3};\n"
                        : "+f"(acc[1][ni][0]), "+f"(acc[1][ni][1]),
                          "+f"(acc[1][ni][2]), "+f"(acc[1][ni][3])
                        : "r"(af1[0]), "r"(af1[1]), "r"(af1[2]), "r"(af1[3]),
                          "r"(bf[nj][h * 2]), "r"(bf[nj][h * 2 + 1]));
                }
            }
        }
        __syncthreads();
    }

    // ---- epilogue: y = acc * scales[n] + bias[n] ----
    #pragma unroll
    for (int mi = 0; mi < 2; ++mi) {
        const int r0 = mbase + wm * 32 + mi * 16 + (lane >> 2);
        float* o0 = out + (size_t)r0 * N + nbase;
        float* o1 = out + (size_t)(r0 + 8) * N + nbase;
        #pragma unroll
        for (int ni = 0; ni < 8; ++ni) {
            const int gn = wn * 64 + ni * 8 + ((lane & 3) << 1);
            const float s0 = scales[nbase + gn], s1 = scales[nbase + gn + 1];
            const float b0 = bias[nbase + gn],   b1 = bias[nbase + gn + 1];
            float2 v;
            v.x = acc[mi][ni][0] * s0 + b0;
            v.y = acc[mi][ni][1] * s1 + b1;
            *reinterpret_cast<float2*>(o0 + gn) = v;
            v.x = acc[mi][ni][2] * s0 + b0;
            v.y = acc[mi][ni][3] * s1 + b1;
            *reinterpret_cast<float2*>(o1 + gn) = v;
        }
    }
}

extern "C" void kernel_launch(void* const* d_in, const int* in_sizes, int n_in,
                              void* d_out, int out_size)
{
    const float* x      = (const float*) d_in[0];
    const int*   w      = (const int*)   d_in[1];   // int8 values in int32 storage
    const float* scales = (const float*) d_in[2];
    const float* bias   = (const float*) d_in[3];
    float*       out    = (float*)       d_out;

    const int N = in_sizes[2];            // 11008
    const int K = in_sizes[1] / N;        // 4096
    const int M = in_sizes[0] / K;        // 4096

    cudaFuncSetAttribute(w8a16_hmma_kernel,
                         cudaFuncAttributeMaxDynamicSharedMemorySize, SMEMB);

    wprequant_kernel<<<2048, 256>>>(w, (N * K) / 4);
    xprequant_kernel<<<2048, 256>>>(x, (M * K) / 4);
    dim3 grid(N / BN, M / BM);            // 86 x 32
    w8a16_hmma_kernel<<<grid, 256, SMEMB>>>(scales, bias, out, M, N, K);
}

// round 7
// speedup vs baseline: 6.3586x; 1.0254x over previous
#include <cuda_runtime.h>
#include <cuda_fp16.h>
#include <cstdint>

// W8A16 linear, single-pass fp16 mma.sync (compute_103-safe).
// out[M,N] = (x[M,K] @ W[N,K]^T) * scales[N] + bias[N]
//   Prequant: W int8-in-int32 -> fp16 (exact); x fp32 -> fp16 (rel err 2^-11).
//   GEMM: CTA 128x128, BK=64, 8 warps x (32x64), cp.async 3-stage pipeline
//   (single __syncthreads per chunk), ldmatrix non-trans fragments,
//   mma.sync.m16n8k16.f32.f16.f16.f32.

#define GK 4096
#define GM 4096
#define GN 11008

__device__ __half g_xh[(size_t)GM * GK];
__device__ __half g_wh[(size_t)GN * GK];

// ---------------- helpers ----------------
__device__ __forceinline__ uint32_t s2u(const void* p) {
    uint32_t a;
    asm("{ .reg .u64 t; cvta.to.shared.u64 t, %1; cvt.u32.u64 %0, t; }" : "=r"(a) : "l"(p));
    return a;
}
#define CP_ASYNC16(dst, src) \
    asm volatile("cp.async.cg.shared.global [%0], [%1], 16;" :: "r"(dst), "l"(src))
#define CP_COMMIT() asm volatile("cp.async.commit_group;" ::: "memory")
#define CP_WAIT(n)  asm volatile("cp.async.wait_group %0;" :: "n"(n) : "memory")

#define LDSM_X4(r0, r1, r2, r3, a)                                              \
    asm volatile("ldmatrix.sync.aligned.m8n8.x4.shared.b16 {%0,%1,%2,%3}, [%4];" \
                 : "=r"(r0), "=r"(r1), "=r"(r2), "=r"(r3) : "r"(a))

// ---------------- prequant ----------------
__global__ void wprequant_kernel(const int* __restrict__ w, int n4) {
    int stride = gridDim.x * blockDim.x;
    for (int i = blockIdx.x * blockDim.x + threadIdx.x; i < n4; i += stride) {
        int4 v = reinterpret_cast<const int4*>(w)[i];
        __half2 p0 = __floats2half2_rn((float)v.x, (float)v.y);   // exact
        __half2 p1 = __floats2half2_rn((float)v.z, (float)v.w);
        uint2 pk;
        pk.x = *reinterpret_cast<uint32_t*>(&p0);
        pk.y = *reinterpret_cast<uint32_t*>(&p1);
        reinterpret_cast<uint2*>(g_wh)[i] = pk;
    }
}

__global__ void xprequant_kernel(const float* __restrict__ x, int n4) {
    int stride = gridDim.x * blockDim.x;
    for (int i = blockIdx.x * blockDim.x + threadIdx.x; i < n4; i += stride) {
        float4 v = reinterpret_cast<const float4*>(x)[i];
        __half2 p0 = __floats2half2_rn(v.x, v.y);
        __half2 p1 = __floats2half2_rn(v.z, v.w);
        uint2 pk;
        pk.x = *reinterpret_cast<uint32_t*>(&p0);
        pk.y = *reinterpret_cast<uint32_t*>(&p1);
        reinterpret_cast<uint2*>(g_xh)[i] = pk;
    }
}

// ---------------- GEMM ----------------
#define BM 128
#define BN 128
#define BK 64
#define ATILE 16384                 // 128 rows x 128 B
#define STAGEB 32768                // A + B
#define NSTAGE 3
#define SMEMB  (NSTAGE * STAGEB)    // 98304

__global__ __launch_bounds__(256, 2)
void w8a16_hmma_kernel(const float* __restrict__ scales,
                       const float* __restrict__ bias,
                       float* __restrict__ out,
                       int M, int N, int K)
{
    extern __shared__ char sm[];
    const uint32_t sb = s2u(sm);
    const int tid  = threadIdx.x;
    const int lane = tid & 31;
    const int warp = tid >> 5;
    const int wm = warp >> 1;            // 0..3
    const int wn = warp & 1;             // 0..1

    const int mbase = blockIdx.y * BM;
    const int nbase = blockIdx.x * BN;

    const __half* ag  = g_xh + (size_t)mbase * K;
    const __half* bgp = g_wh + (size_t)nbase * K;

    float acc[2][8][4];
    #pragma unroll
    for (int mi = 0; mi < 2; ++mi)
        #pragma unroll
        for (int ni = 0; ni < 8; ++ni)
            #pragma unroll
            for (int c = 0; c < 4; ++c)
                acc[mi][ni][c] = 0.0f;

    // ldmatrix lane address components (non-trans x4 for both operands)
    const int a_rl = (lane & 7) + ((lane >> 3) & 1) * 8;   // row within m16
    const int a_cb = lane >> 4;                            // k8-chunk select
    const int b_rl = (lane & 7) + ((lane >> 4) << 3);      // row within n16
    const int b_cb = (lane >> 3) & 1;

    const int ar0 = wm * 32 + a_rl;            // mi=0 row
    const int ar1 = ar0 + 16;                  // mi=1 row
    const uint32_t arow0 = (uint32_t)ar0 * 128, am0 = (uint32_t)(ar0 & 7);
    const uint32_t arow1 = (uint32_t)ar1 * 128, am1 = (uint32_t)(ar1 & 7);

    uint32_t brow[4], bm7[4];
    #pragma unroll
    for (int nj = 0; nj < 4; ++nj) {
        int r = wn * 64 + nj * 16 + b_rl;
        brow[nj] = (uint32_t)r * 128;
        bm7[nj]  = (uint32_t)(r & 7);
    }

    const int nch = K / BK;                    // 64

    // issue one stage: 2048 x 16B chunks, 8 per thread
    #define ISSUE_STAGE(st, k0) do {                                             \
        uint32_t dstb = sb + (st) * STAGEB;                                      \
        _Pragma("unroll")                                                        \
        for (int cc = 0; cc < 8; ++cc) {                                         \
            int cid  = tid + cc * 256;          /* 0..2047 */                    \
            int tile = cid >> 10;               /* 0=A 1=B */                    \
            int rem  = cid & 1023;                                               \
            int row  = rem >> 3;                                                 \
            int c    = rem & 7;                                                  \
            const __half* src = (tile ? bgp : ag) + (size_t)row * K + (k0) + c * 8; \
            uint32_t dst = dstb + tile * ATILE + row * 128 +                     \
                           ((uint32_t)(c ^ (row & 7)) << 4);                     \
            CP_ASYNC16(dst, src);                                                \
        }                                                                        \
        CP_COMMIT();                                                             \
    } while (0)

    ISSUE_STAGE(0, 0);
    ISSUE_STAGE(1, BK);

    int stage = 0;
    for (int i = 0; i < nch; ++i) {
        if (i + 1 < nch) { CP_WAIT(1); } else { CP_WAIT(0); }
        __syncthreads();
        if (i + 2 < nch) {
            int st2 = stage + 2;
            if (st2 >= NSTAGE) st2 -= NSTAGE;
            ISSUE_STAGE(st2, (i + 2) * BK);
        }

        const uint32_t as = sb + stage * STAGEB;
        const uint32_t bs = as + ATILE;

        #pragma unroll
        for (int ks = 0; ks < 4; ++ks) {
            const uint32_t kc2 = (uint32_t)(ks * 2);

            uint32_t bf[4][4];
            #pragma unroll
            for (int nj = 0; nj < 4; ++nj) {
                uint32_t addr = bs + brow[nj] + (((kc2 + b_cb) ^ bm7[nj]) << 4);
                LDSM_X4(bf[nj][0], bf[nj][1], bf[nj][2], bf[nj][3], addr);
            }

            uint32_t af0[4], af1[4];
            {
                uint32_t addr = as + arow0 + (((kc2 + a_cb) ^ am0) << 4);
                LDSM_X4(af0[0], af0[1], af0[2], af0[3], addr);
                addr = as + arow1 + (((kc2 + a_cb) ^ am1) << 4);
                LDSM_X4(af1[0], af1[1], af1[2], af1[3], addr);
            }

            #pragma unroll
            for (int nj = 0; nj < 4; ++nj) {
                #pragma unroll
                for (int h = 0; h < 2; ++h) {       // ni = nj*2 + h
                    const int ni = nj * 2 + h;
                    asm volatile(
                        "mma.sync.aligned.m16n8k16.row.col.f32.f16.f16.f32 "
                        "{%0,%1,%2,%3}, {%4,%5,%6,%7}, {%8,%9}, {%0,%1,%2,%3};\n"
                        : "+f"(acc[0][ni][0]), "+f"(acc[0][ni][1]),
                          "+f"(acc[0][ni][2]), "+f"(acc[0][ni][3])
                        : "r"(af0[0]), "r"(af0[1]), "r"(af0[2]), "r"(af0[3]),
                          "r"(bf[nj][h * 2]), "r"(bf[nj][h * 2 + 1]));
                    asm volatile(
                        "mma.sync.aligned.m16n8k16.row.col.f32.f16.f16.f32 "
                        "{%0,%1,%2,%3}, {%4,%5,%6,%7}, {%8,%9}, {%0,%1,%2,%3};\n"
                        : "+f"(acc[1][ni][0]), "+f"(acc[1][ni][1]),
                          "+f"(acc[1][ni][2]), "+f"(acc[1][ni][3])
                        : "r"(af1[0]), "r"(af1[1]), "r"(af1[2]), "r"(af1[3]),
                          "r"(bf[nj][h * 2]), "r"(bf[nj][h * 2 + 1]));
                }
            }
        }

        if (++stage == NSTAGE) stage = 0;
    }

    // ---- epilogue: y = acc * scales[n] + bias[n] ----
    #pragma unroll
    for (int mi = 0; mi < 2; ++mi) {
        const int r0 = mbase + wm * 32 + mi * 16 + (lane >> 2);
        float* o0 = out + (size_t)r0 * N + nbase;
        float* o1 = out + (size_t)(r0 + 8) * N + nbase;
        #pragma unroll
        for (int ni = 0; ni < 8; ++ni) {
            const int gn = wn * 64 + ni * 8 + ((lane & 3) << 1);
            const float s0 = scales[nbase + gn], s1 = scales[nbase + gn + 1];
            const float b0 = bias[nbase + gn],   b1 = bias[nbase + gn + 1];
            float2 v;
            v.x = acc[mi][ni][0] * s0 + b0;
            v.y = acc[mi][ni][1] * s1 + b1;
            *reinterpret_cast<float2*>(o0 + gn) = v;
            v.x = acc[mi][ni][2] * s0 + b0;
            v.y = acc[mi][ni][3] * s1 + b1;
            *reinterpret_cast<float2*>(o1 + gn) = v;
        }
    }
}

extern "C" void kernel_launch(void* const* d_in, const int* in_sizes, int n_in,
                              void* d_out, int out_size)
{
    const float* x      = (const float*) d_in[0];
    const int*   w      = (const int*)   d_in[1];   // int8 values in int32 storage
    const float* scales = (const float*) d_in[2];
    const float* bias   = (const float*) d_in[3];
    float*       out    = (float*)       d_out;

    const int N = in_sizes[2];            // 11008
    const int K = in_sizes[1] / N;        // 4096
    const int M = in_sizes[0] / K;        // 4096

    cudaFuncSetAttribute(w8a16_hmma_kernel,
                         cudaFuncAttributeMaxDynamicSharedMemorySize, SMEMB);

    wprequant_kernel<<<2048, 256>>>(w, (N * K) / 4);
    xprequant_kernel<<<2048, 256>>>(x, (M * K) / 4);
    dim3 grid(N / BN, M / BM);            // 86 x 32
    w8a16_hmma_kernel<<<grid, 256, SMEMB>>>(scales, bias, out, M, N, K);
}